// round 4
// baseline (speedup 1.0000x reference)
#include <cuda_runtime.h>
#include <cstdint>

// Causal scaled-dot-product attention, S=8192, D=128, fp32 I/O.
// FlashAttention-2 with mma.sync m16n8k8 TF32 (fp32 accumulate),
// 2-way split-KV for causal load balance + combine kernel.

#define S_LEN   8192
#define DKDIM   128
#define BR      64          // query rows per CTA (16 per warp, 4 warps)
#define BC      64          // keys per iteration
#define KSTRIDE 132         // smem stride (floats) for K tile  -> conflict-free
#define VSTRIDE 136         // smem stride (floats) for V tile  -> conflict-free
#define PSTRIDE 68          // smem stride (floats) for P stage -> conflict-free
#define NQB     (S_LEN / BR)    // 128 query blocks

// Scratch for split-KV partials (static device globals: allocation-free).
__device__ float g_acc[2][S_LEN][DKDIM];   // unnormalized O partials
__device__ float g_m[2][S_LEN];            // running max (log2 domain)
__device__ float g_l[2][S_LEN];            // running denom

__device__ __forceinline__ unsigned f2tf(float x) {
    unsigned r;
    asm("cvt.rna.tf32.f32 %0, %1;" : "=r"(r) : "f"(x));
    return r;
}

__device__ __forceinline__ void mma_tf32(float c[4], const unsigned a[4],
                                         unsigned b0, unsigned b1) {
    asm volatile(
        "mma.sync.aligned.m16n8k8.row.col.f32.tf32.tf32.f32 "
        "{%0,%1,%2,%3}, {%4,%5,%6,%7}, {%8,%9}, {%0,%1,%2,%3};\n"
        : "+f"(c[0]), "+f"(c[1]), "+f"(c[2]), "+f"(c[3])
        : "r"(a[0]), "r"(a[1]), "r"(a[2]), "r"(a[3]), "r"(b0), "r"(b1));
}

__global__ void __launch_bounds__(128)
attn_fwd_kernel(const float* __restrict__ q,
                const float* __restrict__ k,
                const float* __restrict__ v) {
    extern __shared__ float smem[];
    float* Ks = smem;                         // BC x KSTRIDE
    float* Vs = smem + BC * KSTRIDE;          // BC x VSTRIDE
    float* Ps = Vs + BC * VSTRIDE;            // 4 warps x 16 x PSTRIDE

    const int tid  = threadIdx.x;
    const int w    = tid >> 5;
    const int lane = tid & 31;
    const int g    = lane >> 2;   // groupID   (0..7)
    const int t    = lane & 3;    // tid in grp (0..3)

    // Heaviest-first mapping: low blockIdx -> largest q-block.
    const int qb    = (NQB - 1) - (int)(blockIdx.x >> 1);
    const int chunk = (int)(blockIdx.x & 1);
    const int nbt   = qb + 1;                 // total key-blocks for this q-block
    const int nb0   = (nbt + 1) >> 1;
    const int kb_beg = chunk ? nb0 : 0;
    const int kb_end = chunk ? nbt : nb0;

    // fold 1/sqrt(d) and log2(e) into Q -> scores live in log2 domain
    const float QSCALE = 0.08838834764831845f * 1.4426950408889634f;

    // ---- Q fragments (A operands, 16 rows per warp, full D=128) ----
    const int rowbase = qb * BR + w * 16;
    unsigned qf[16][4];
    {
        const float* qg  = q + (size_t)(rowbase + g)     * DKDIM + t;
        const float* qg8 = q + (size_t)(rowbase + g + 8) * DKDIM + t;
        #pragma unroll
        for (int kt = 0; kt < 16; kt++) {
            qf[kt][0] = f2tf(qg [8 * kt    ] * QSCALE);
            qf[kt][1] = f2tf(qg8[8 * kt    ] * QSCALE);
            qf[kt][2] = f2tf(qg [8 * kt + 4] * QSCALE);
            qf[kt][3] = f2tf(qg8[8 * kt + 4] * QSCALE);
        }
    }

    float of[16][4];
    #pragma unroll
    for (int nt = 0; nt < 16; nt++) {
        of[nt][0] = 0.f; of[nt][1] = 0.f; of[nt][2] = 0.f; of[nt][3] = 0.f;
    }
    float m0 = -1e30f, m1 = -1e30f, l0 = 0.f, l1 = 0.f;

    float* Pw = Ps + w * 16 * PSTRIDE;

    for (int kb = kb_beg; kb < kb_end; kb++) {
        __syncthreads();   // previous iter's smem reads complete
        // ---- load K,V tile (BC x D), convert to tf32 ----
        {
            const float4* kg = (const float4*)(k + (size_t)kb * BC * DKDIM);
            const float4* vg = (const float4*)(v + (size_t)kb * BC * DKDIM);
            #pragma unroll
            for (int i = 0; i < 16; i++) {
                int lin = tid + i * 128;          // 0..2047 float4s
                int r   = lin >> 5;
                int c4  = lin & 31;
                float4 kk4 = kg[lin];
                float4 vv4 = vg[lin];
                float* kd = Ks + r * KSTRIDE + c4 * 4;
                kd[0] = __uint_as_float(f2tf(kk4.x));
                kd[1] = __uint_as_float(f2tf(kk4.y));
                kd[2] = __uint_as_float(f2tf(kk4.z));
                kd[3] = __uint_as_float(f2tf(kk4.w));
                float* vd = Vs + r * VSTRIDE + c4 * 4;
                vd[0] = __uint_as_float(f2tf(vv4.x));
                vd[1] = __uint_as_float(f2tf(vv4.y));
                vd[2] = __uint_as_float(f2tf(vv4.z));
                vd[3] = __uint_as_float(f2tf(vv4.w));
            }
        }
        __syncthreads();

        // ---- S = Q K^T  (16 x 64 per warp) ----
        float sf[8][4];
        #pragma unroll
        for (int nt = 0; nt < 8; nt++) {
            sf[nt][0] = 0.f; sf[nt][1] = 0.f; sf[nt][2] = 0.f; sf[nt][3] = 0.f;
        }
        #pragma unroll
        for (int kt = 0; kt < 16; kt++) {
            #pragma unroll
            for (int nt = 0; nt < 8; nt++) {
                const float* kp = Ks + (8 * nt + g) * KSTRIDE + 8 * kt + t;
                unsigned b0 = __float_as_uint(kp[0]);
                unsigned b1 = __float_as_uint(kp[4]);
                mma_tf32(sf[nt], qf[kt], b0, b1);
            }
        }

        // ---- causal mask on diagonal block ----
        if (kb == qb) {
            const int r0 = 16 * w + g;
            #pragma unroll
            for (int nt = 0; nt < 8; nt++) {
                int lc = 8 * nt + 2 * t;
                if (lc     > r0    ) sf[nt][0] = -1e30f;
                if (lc + 1 > r0    ) sf[nt][1] = -1e30f;
                if (lc     > r0 + 8) sf[nt][2] = -1e30f;
                if (lc + 1 > r0 + 8) sf[nt][3] = -1e30f;
            }
        }

        // ---- online softmax (log2 domain) ----
        float mx0 = -1e30f, mx1 = -1e30f;
        #pragma unroll
        for (int nt = 0; nt < 8; nt++) {
            mx0 = fmaxf(mx0, fmaxf(sf[nt][0], sf[nt][1]));
            mx1 = fmaxf(mx1, fmaxf(sf[nt][2], sf[nt][3]));
        }
        mx0 = fmaxf(mx0, __shfl_xor_sync(0xffffffffu, mx0, 1));
        mx0 = fmaxf(mx0, __shfl_xor_sync(0xffffffffu, mx0, 2));
        mx1 = fmaxf(mx1, __shfl_xor_sync(0xffffffffu, mx1, 1));
        mx1 = fmaxf(mx1, __shfl_xor_sync(0xffffffffu, mx1, 2));

        const float mn0 = fmaxf(m0, mx0);
        const float mn1 = fmaxf(m1, mx1);
        const float a0  = exp2f(m0 - mn0);
        const float a1  = exp2f(m1 - mn1);

        float s0 = 0.f, s1 = 0.f;
        #pragma unroll
        for (int nt = 0; nt < 8; nt++) {
            float p0 = exp2f(sf[nt][0] - mn0);
            float p1 = exp2f(sf[nt][1] - mn0);
            float p2 = exp2f(sf[nt][2] - mn1);
            float p3 = exp2f(sf[nt][3] - mn1);
            s0 += p0 + p1;
            s1 += p2 + p3;
            int c0 = 8 * nt + 2 * t;
            Pw[ g      * PSTRIDE + c0    ] = __uint_as_float(f2tf(p0));
            Pw[ g      * PSTRIDE + c0 + 1] = __uint_as_float(f2tf(p1));
            Pw[(g + 8) * PSTRIDE + c0    ] = __uint_as_float(f2tf(p2));
            Pw[(g + 8) * PSTRIDE + c0 + 1] = __uint_as_float(f2tf(p3));
        }
        s0 += __shfl_xor_sync(0xffffffffu, s0, 1);
        s0 += __shfl_xor_sync(0xffffffffu, s0, 2);
        s1 += __shfl_xor_sync(0xffffffffu, s1, 1);
        s1 += __shfl_xor_sync(0xffffffffu, s1, 2);
        l0 = l0 * a0 + s0;
        l1 = l1 * a1 + s1;
        m0 = mn0;
        m1 = mn1;

        #pragma unroll
        for (int nt = 0; nt < 16; nt++) {
            of[nt][0] *= a0; of[nt][1] *= a0;
            of[nt][2] *= a1; of[nt][3] *= a1;
        }
        __syncwarp();   // P visible to all lanes of this warp

        // ---- O += P V  (16 x 128 per warp) ----
        #pragma unroll
        for (int kt = 0; kt < 8; kt++) {
            unsigned pa[4];
            pa[0] = __float_as_uint(Pw[ g      * PSTRIDE + 8 * kt + t    ]);
            pa[1] = __float_as_uint(Pw[(g + 8) * PSTRIDE + 8 * kt + t    ]);
            pa[2] = __float_as_uint(Pw[ g      * PSTRIDE + 8 * kt + t + 4]);
            pa[3] = __float_as_uint(Pw[(g + 8) * PSTRIDE + 8 * kt + t + 4]);
            #pragma unroll
            for (int nt = 0; nt < 16; nt++) {
                unsigned vb0 = __float_as_uint(Vs[(8 * kt + t    ) * VSTRIDE + 8 * nt + g]);
                unsigned vb1 = __float_as_uint(Vs[(8 * kt + t + 4) * VSTRIDE + 8 * nt + g]);
                mma_tf32(of[nt], pa, vb0, vb1);
            }
        }
    }

    // ---- epilogue: write unnormalized partials + stats ----
    {
        float* accg  = &g_acc[chunk][rowbase + g    ][0];
        float* accg8 = &g_acc[chunk][rowbase + g + 8][0];
        #pragma unroll
        for (int nt = 0; nt < 16; nt++) {
            int c0 = 8 * nt + 2 * t;
            *(float2*)(accg  + c0) = make_float2(of[nt][0], of[nt][1]);
            *(float2*)(accg8 + c0) = make_float2(of[nt][2], of[nt][3]);
        }
        if (t == 0) {
            g_m[chunk][rowbase + g    ] = m0;
            g_l[chunk][rowbase + g    ] = l0;
            g_m[chunk][rowbase + g + 8] = m1;
            g_l[chunk][rowbase + g + 8] = l1;
        }
    }
}

__global__ void __launch_bounds__(256)
combine_kernel(float* __restrict__ out) {
    int idx = blockIdx.x * 256 + threadIdx.x;   // 0 .. S*D-1
    int row = idx >> 7;
    int d   = idx & (DKDIM - 1);
    float m0 = g_m[0][row], m1 = g_m[1][row];
    float mm = fmaxf(m0, m1);
    float w0 = exp2f(m0 - mm);
    float w1 = exp2f(m1 - mm);
    float l  = w0 * g_l[0][row] + w1 * g_l[1][row];
    out[idx] = (w0 * g_acc[0][row][d] + w1 * g_acc[1][row][d]) / l;
}

extern "C" void kernel_launch(void* const* d_in, const int* in_sizes, int n_in,
                              void* d_out, int out_size) {
    const float* q = (const float*)d_in[0];
    const float* k = (const float*)d_in[1];
    const float* v = (const float*)d_in[2];
    float* out = (float*)d_out;

    const int smem_bytes = (BC * KSTRIDE + BC * VSTRIDE + 4 * 16 * PSTRIDE) * 4; // 86016
    cudaFuncSetAttribute(attn_fwd_kernel,
                         cudaFuncAttributeMaxDynamicSharedMemorySize, smem_bytes);

    attn_fwd_kernel<<<2 * NQB, 128, smem_bytes>>>(q, k, v);
    combine_kernel<<<(S_LEN * DKDIM) / 256, 256>>>(out);
}

// round 5
// speedup vs baseline: 1.6282x; 1.6282x over previous
#include <cuda_runtime.h>
#include <cstdint>

// Causal attention S=8192 D=128 fp32. FA2 with mma.sync m16n8k8 TF32.
// Round 5: prepacked tf32 fragment tiles + cp.async + persistent work stealing.

#define S_LEN   8192
#define DKDIM   128
#define BR      64
#define BC      64
#define NKB     (S_LEN / BC)     // 128 key blocks
#define NQB     (S_LEN / BR)     // 128 query blocks
#define PSTRIDE 68
#define STRIPE_KB 16             // key-blocks per work unit
#define NSLOT   8                // max stripes per q-block
#define NUNITS  576              // sum_{qb} ceil((qb+1)/16)
#define GRID_MAIN 304
#define TILE_F  8192             // floats per packed 64x128 tile (32KB)

// Packed tf32 fragment tiles (written by prep kernel).
__device__ float g_KB[(size_t)NKB * TILE_F];
__device__ float g_VB[(size_t)NKB * TILE_F];
// Split-KV partials.
__device__ float g_acc[NSLOT][S_LEN][DKDIM];
__device__ float g_m[NSLOT][S_LEN];
__device__ float g_l[NSLOT][S_LEN];
__device__ int   g_ctr;

__device__ __forceinline__ unsigned f2tf(float x) {
    unsigned r;
    asm("cvt.rna.tf32.f32 %0, %1;" : "=r"(r) : "f"(x));
    return r;
}
__device__ __forceinline__ float ex2(float x) {
    float r;
    asm("ex2.approx.ftz.f32 %0, %1;" : "=f"(r) : "f"(x));
    return r;
}
__device__ __forceinline__ void mma_tf32(float c[4], const unsigned a[4],
                                         unsigned b0, unsigned b1) {
    asm volatile(
        "mma.sync.aligned.m16n8k8.row.col.f32.tf32.tf32.f32 "
        "{%0,%1,%2,%3}, {%4,%5,%6,%7}, {%8,%9}, {%0,%1,%2,%3};\n"
        : "+f"(c[0]), "+f"(c[1]), "+f"(c[2]), "+f"(c[3])
        : "r"(a[0]), "r"(a[1]), "r"(a[2]), "r"(a[3]), "r"(b0), "r"(b1));
}

// ---------------------------------------------------------------------------
// Pre-pass: convert K,V to tf32 and pack into mma B-fragment layout.
// K tile (QK^T):  float index i = (((nt*8 + kt2)*32 + lane)*4 + c)
//   kt = 2*kt2 + (c>>1), sel = c&1, g=lane>>2, t=lane&3
//   value = K[64*kb + 8*nt + g][8*kt + t + 4*sel]
// V tile (P·V):   float index i = (((kt*8 + nt2)*32 + lane)*4 + c)
//   nt = 2*nt2 + (c>>1), sel = c&1
//   value = V[64*kb + 8*kt + t + 4*sel][8*nt + g]
// ---------------------------------------------------------------------------
__global__ void __launch_bounds__(256)
prep_kernel(const float* __restrict__ k, const float* __restrict__ v) {
    unsigned e = blockIdx.x * 256u + threadIdx.x;   // 0 .. 2*2^20-1
    if (e == 0) g_ctr = 0;
    unsigned which = e >> 20;
    unsigned i = e & 0xFFFFFu;
    unsigned c    = i & 3u;
    unsigned lane = (i >> 2) & 31u;
    unsigned f2   = (i >> 7) & 7u;
    unsigned f1   = (i >> 10) & 7u;
    unsigned kb   = i >> 13;
    unsigned g = lane >> 2, t = lane & 3u;
    unsigned sel = c & 1u, half = c >> 1;
    if (which == 0) {
        unsigned kt  = 2u * f2 + half;              // f2 = kt2, f1 = nt
        unsigned row = 64u * kb + 8u * f1 + g;
        unsigned col = 8u * kt + t + 4u * sel;
        g_KB[i] = __uint_as_float(f2tf(k[(size_t)row * DKDIM + col]));
    } else {
        unsigned nt  = 2u * f2 + half;              // f2 = nt2, f1 = kt
        unsigned row = 64u * kb + 8u * f1 + t + 4u * sel;
        unsigned col = 8u * nt + g;
        g_VB[i] = __uint_as_float(f2tf(v[(size_t)row * DKDIM + col]));
    }
}

// ---------------------------------------------------------------------------
// Main kernel: persistent CTAs, atomic stealing of (qb, stripe) units.
// ---------------------------------------------------------------------------
__global__ void __launch_bounds__(128)
attn_fwd_kernel(const float* __restrict__ q) {
    extern __shared__ float smem[];
    float* Ks = smem;                        // 8192 floats (packed K tile)
    float* Vs = smem + TILE_F;               // 8192 floats (packed V tile)
    float* Ps = smem + 2 * TILE_F;           // 4*16*PSTRIDE floats
    int*   bc = (int*)(smem + 2 * TILE_F + 4 * 16 * PSTRIDE);

    const unsigned ks_b = (unsigned)__cvta_generic_to_shared(Ks);
    const unsigned vs_b = (unsigned)__cvta_generic_to_shared(Vs);

    const int tid  = threadIdx.x;
    const int w    = tid >> 5;
    const int lane = tid & 31;
    const int g    = lane >> 2;
    const int t    = lane & 3;
    const float QSCALE = 0.08838834764831845f * 1.4426950408889634f;

    float* Pw = Ps + w * 16 * PSTRIDE;
    const float4* Kf = (const float4*)Ks;
    const float4* Vf = (const float4*)Vs;

    for (;;) {
        if (tid == 0) *bc = atomicAdd(&g_ctr, 1);
        __syncthreads();
        const int u = *bc;
        if (u >= NUNITS) break;

        // unit -> (qb, stripe)
        int rem = u, qb = NQB - 1;
        for (;;) {
            int nc = (qb + 16) >> 4;     // ceil((qb+1)/16)
            if (rem < nc) break;
            rem -= nc; qb--;
        }
        const int stripe = rem;
        const int kb0 = stripe * STRIPE_KB;
        const int kb_lim = qb + 1;
        const int kb1 = (kb0 + STRIPE_KB < kb_lim) ? (kb0 + STRIPE_KB) : kb_lim;

        // Q fragments for this unit
        const int rowbase = qb * BR + w * 16;
        unsigned qf[16][4];
        {
            const float* qg  = q + (size_t)(rowbase + g)     * DKDIM + t;
            const float* qg8 = q + (size_t)(rowbase + g + 8) * DKDIM + t;
            #pragma unroll
            for (int kt = 0; kt < 16; kt++) {
                qf[kt][0] = f2tf(qg [8 * kt    ] * QSCALE);
                qf[kt][1] = f2tf(qg8[8 * kt    ] * QSCALE);
                qf[kt][2] = f2tf(qg [8 * kt + 4] * QSCALE);
                qf[kt][3] = f2tf(qg8[8 * kt + 4] * QSCALE);
            }
        }

        float of[16][4];
        #pragma unroll
        for (int nt = 0; nt < 16; nt++) {
            of[nt][0] = 0.f; of[nt][1] = 0.f; of[nt][2] = 0.f; of[nt][3] = 0.f;
        }
        float m0 = -1e30f, m1 = -1e30f, l0 = 0.f, l1 = 0.f;

        for (int kb = kb0; kb < kb1; kb++) {
            // ---- async tile load (linear 16B copies of prepacked tiles) ----
            const float* ksrc = g_KB + (size_t)kb * TILE_F;
            const float* vsrc = g_VB + (size_t)kb * TILE_F;
            #pragma unroll
            for (int i = 0; i < 16; i++) {
                int off = (tid + i * 128) * 4;   // float offset, 16B aligned
                asm volatile("cp.async.cg.shared.global [%0], [%1], 16;\n"
                             :: "r"(ks_b + off * 4), "l"(ksrc + off));
                asm volatile("cp.async.cg.shared.global [%0], [%1], 16;\n"
                             :: "r"(vs_b + off * 4), "l"(vsrc + off));
            }
            asm volatile("cp.async.commit_group;\n");
            asm volatile("cp.async.wait_group 0;\n");
            __syncthreads();

            // ---- S = Q K^T : packed fragments, LDS.128 per 2 mmas ----
            float sf[8][4];
            #pragma unroll
            for (int nt = 0; nt < 8; nt++) {
                sf[nt][0] = 0.f; sf[nt][1] = 0.f; sf[nt][2] = 0.f; sf[nt][3] = 0.f;
            }
            #pragma unroll
            for (int nt = 0; nt < 8; nt++) {
                #pragma unroll
                for (int kt2 = 0; kt2 < 8; kt2++) {
                    float4 ch = Kf[(nt * 8 + kt2) * 32 + lane];
                    mma_tf32(sf[nt], qf[2 * kt2],
                             __float_as_uint(ch.x), __float_as_uint(ch.y));
                    mma_tf32(sf[nt], qf[2 * kt2 + 1],
                             __float_as_uint(ch.z), __float_as_uint(ch.w));
                }
            }

            // ---- causal mask on diagonal block ----
            if (kb == qb) {
                const int r0 = 16 * w + g;
                #pragma unroll
                for (int nt = 0; nt < 8; nt++) {
                    int lc = 8 * nt + 2 * t;
                    if (lc     > r0    ) sf[nt][0] = -1e30f;
                    if (lc + 1 > r0    ) sf[nt][1] = -1e30f;
                    if (lc     > r0 + 8) sf[nt][2] = -1e30f;
                    if (lc + 1 > r0 + 8) sf[nt][3] = -1e30f;
                }
            }

            // ---- online softmax (log2 domain) ----
            float mx0 = -1e30f, mx1 = -1e30f;
            #pragma unroll
            for (int nt = 0; nt < 8; nt++) {
                mx0 = fmaxf(mx0, fmaxf(sf[nt][0], sf[nt][1]));
                mx1 = fmaxf(mx1, fmaxf(sf[nt][2], sf[nt][3]));
            }
            mx0 = fmaxf(mx0, __shfl_xor_sync(0xffffffffu, mx0, 1));
            mx0 = fmaxf(mx0, __shfl_xor_sync(0xffffffffu, mx0, 2));
            mx1 = fmaxf(mx1, __shfl_xor_sync(0xffffffffu, mx1, 1));
            mx1 = fmaxf(mx1, __shfl_xor_sync(0xffffffffu, mx1, 2));

            const float mn0 = fmaxf(m0, mx0);
            const float mn1 = fmaxf(m1, mx1);
            const float a0  = ex2(m0 - mn0);
            const float a1  = ex2(m1 - mn1);

            float s0 = 0.f, s1 = 0.f;
            #pragma unroll
            for (int nt = 0; nt < 8; nt++) {
                float p0 = ex2(sf[nt][0] - mn0);
                float p1 = ex2(sf[nt][1] - mn0);
                float p2 = ex2(sf[nt][2] - mn1);
                float p3 = ex2(sf[nt][3] - mn1);
                s0 += p0 + p1;
                s1 += p2 + p3;
                int c0 = 8 * nt + 2 * t;
                Pw[ g      * PSTRIDE + c0    ] = __uint_as_float(f2tf(p0));
                Pw[ g      * PSTRIDE + c0 + 1] = __uint_as_float(f2tf(p1));
                Pw[(g + 8) * PSTRIDE + c0    ] = __uint_as_float(f2tf(p2));
                Pw[(g + 8) * PSTRIDE + c0 + 1] = __uint_as_float(f2tf(p3));
            }
            s0 += __shfl_xor_sync(0xffffffffu, s0, 1);
            s0 += __shfl_xor_sync(0xffffffffu, s0, 2);
            s1 += __shfl_xor_sync(0xffffffffu, s1, 1);
            s1 += __shfl_xor_sync(0xffffffffu, s1, 2);
            l0 = l0 * a0 + s0;
            l1 = l1 * a1 + s1;
            m0 = mn0;
            m1 = mn1;

            #pragma unroll
            for (int nt = 0; nt < 16; nt++) {
                of[nt][0] *= a0; of[nt][1] *= a0;
                of[nt][2] *= a1; of[nt][3] *= a1;
            }
            __syncwarp();

            // ---- O += P V : packed V fragments ----
            #pragma unroll
            for (int kt = 0; kt < 8; kt++) {
                unsigned pa[4];
                pa[0] = __float_as_uint(Pw[ g      * PSTRIDE + 8 * kt + t    ]);
                pa[1] = __float_as_uint(Pw[(g + 8) * PSTRIDE + 8 * kt + t    ]);
                pa[2] = __float_as_uint(Pw[ g      * PSTRIDE + 8 * kt + t + 4]);
                pa[3] = __float_as_uint(Pw[(g + 8) * PSTRIDE + 8 * kt + t + 4]);
                #pragma unroll
                for (int nt2 = 0; nt2 < 8; nt2++) {
                    float4 ch = Vf[(kt * 8 + nt2) * 32 + lane];
                    mma_tf32(of[2 * nt2],     pa,
                             __float_as_uint(ch.x), __float_as_uint(ch.y));
                    mma_tf32(of[2 * nt2 + 1], pa,
                             __float_as_uint(ch.z), __float_as_uint(ch.w));
                }
            }
            __syncthreads();   // tile consumed; safe to overwrite next iter
        }

        // ---- epilogue: unnormalized partials into this unit's slot ----
        {
            float* accg  = &g_acc[stripe][rowbase + g    ][0];
            float* accg8 = &g_acc[stripe][rowbase + g + 8][0];
            #pragma unroll
            for (int nt = 0; nt < 16; nt++) {
                int c0 = 8 * nt + 2 * t;
                *(float2*)(accg  + c0) = make_float2(of[nt][0], of[nt][1]);
                *(float2*)(accg8 + c0) = make_float2(of[nt][2], of[nt][3]);
            }
            if (t == 0) {
                g_m[stripe][rowbase + g    ] = m0;
                g_l[stripe][rowbase + g    ] = l0;
                g_m[stripe][rowbase + g + 8] = m1;
                g_l[stripe][rowbase + g + 8] = l1;
            }
        }
    }
}

__global__ void __launch_bounds__(256)
combine_kernel(float* __restrict__ out) {
    int idx = blockIdx.x * 256 + threadIdx.x;   // 0 .. S*D-1
    int row = idx >> 7;
    int d   = idx & (DKDIM - 1);
    int qb  = row >> 6;
    int nc  = (qb + 16) >> 4;                   // slots used for this q-block
    float mm = g_m[0][row];
    for (int c = 1; c < nc; c++) mm = fmaxf(mm, g_m[c][row]);
    float L = 0.f, acc = 0.f;
    for (int c = 0; c < nc; c++) {
        float wgt = ex2(g_m[c][row] - mm);
        L   += wgt * g_l[c][row];
        acc += wgt * g_acc[c][row][d];
    }
    out[idx] = acc / L;
}

extern "C" void kernel_launch(void* const* d_in, const int* in_sizes, int n_in,
                              void* d_out, int out_size) {
    const float* q = (const float*)d_in[0];
    const float* k = (const float*)d_in[1];
    const float* v = (const float*)d_in[2];
    float* out = (float*)d_out;

    const int smem_bytes = (2 * TILE_F + 4 * 16 * PSTRIDE) * 4 + 16; // 82960
    cudaFuncSetAttribute(attn_fwd_kernel,
                         cudaFuncAttributeMaxDynamicSharedMemorySize, smem_bytes);

    prep_kernel<<<8192, 256>>>(k, v);
    attn_fwd_kernel<<<GRID_MAIN, 128, smem_bytes>>>(q);
    combine_kernel<<<(S_LEN * DKDIM) / 256, 256>>>(out);
}